// round 2
// baseline (speedup 1.0000x reference)
#include <cuda_runtime.h>
#include <cuda_bf16.h>
#include <cstdint>

// ---------------------------------------------------------------------------
// Problem constants
// ---------------------------------------------------------------------------
static constexpr int B_  = 4;
static constexpr int C_  = 64;
static constexpr int H_  = 256;
static constexpr int W_  = 512;
static constexpr int HW  = H_ * W_;               // 131072
static constexpr int SW_ = 3 * W_;                // 1536
static constexpr int NIDX = 3 * H_ * 3 * W_;      // 3538944
static constexpr int TILE_P = 128;
static constexpr int TILES_PER_B = HW / TILE_P;   // 1024
static constexpr int N_TILES = B_ * TILES_PER_B;  // 4096
static constexpr int THREADS = 256;

// A tiles: 128 rows (pixels) x 64 ci, row pitch 68 floats (conflict-free)
static constexpr int A_PITCH = 68;
static constexpr int A_BYTES = TILE_P * A_PITCH * 4;     // 34816
// W: per tap 32 (ks*4+tig) rows x 64 co float2, pitch 68 float2 (conflict-free)
static constexpr int W_PITCH = 68;                        // in float2 units
static constexpr int W_TAP_F2 = 32 * W_PITCH;             // 2176 float2 per tap
static constexpr int W_BYTES = 9 * W_TAP_F2 * 8;          // 156672

static constexpr int SMEM_BIAS = 0;                       // 256 B
static constexpr int SMEM_W    = 256;                     // 156672 B
static constexpr int SMEM_A0   = 157696;                  // 1024-aligned
static constexpr int SMEM_A1   = SMEM_A0 + A_BYTES;       // 192512
static constexpr int SMEM_TOTAL = SMEM_A1 + A_BYTES;      // 227328
static constexpr int STG_PITCH = 132;                     // output staging pitch

__device__ int   g_idx_is64;
__device__ int   g_idx32[NIDX];
__device__ float g_xt[(size_t)B_ * HW * C_];   // [B][HW][C], tf32-rounded

// ---------------------------------------------------------------------------
// helpers
// ---------------------------------------------------------------------------
__device__ __forceinline__ float to_tf32(float x) {
    uint32_t u;
    asm("cvt.rna.tf32.f32 %0, %1;" : "=r"(u) : "f"(x));
    return __uint_as_float(u);
}

__device__ __forceinline__ void mma_tf32(float* c, const float* a, float b0, float b1) {
    asm volatile(
        "mma.sync.aligned.m16n8k8.row.col.f32.tf32.tf32.f32 "
        "{%0,%1,%2,%3}, {%4,%5,%6,%7}, {%8,%9}, {%0,%1,%2,%3};"
        : "+f"(c[0]), "+f"(c[1]), "+f"(c[2]), "+f"(c[3])
        : "r"(__float_as_uint(a[0])), "r"(__float_as_uint(a[1])),
          "r"(__float_as_uint(a[2])), "r"(__float_as_uint(a[3])),
          "r"(__float_as_uint(b0)),  "r"(__float_as_uint(b1)));
}

// ---------------------------------------------------------------------------
// Kernel 0: detect int64 vs int32 index dtype
// ---------------------------------------------------------------------------
__global__ void detect_kernel(const unsigned int* __restrict__ w) {
    if (threadIdx.x == 0) {
        int is64 = 1;
        for (int i = 0; i < 64; ++i)
            if (w[2 * i + 1] != 0u) { is64 = 0; break; }
        g_idx_is64 = is64;
    }
}

// ---------------------------------------------------------------------------
// Kernel 1: convert idx to int32
// ---------------------------------------------------------------------------
__global__ void idx_convert(const void* __restrict__ idx_raw) {
    int i = blockIdx.x * blockDim.x + threadIdx.x;
    if (i < NIDX) {
        g_idx32[i] = g_idx_is64 ? (int)((const long long*)idx_raw)[i]
                                : ((const int*)idx_raw)[i];
    }
}

// ---------------------------------------------------------------------------
// Kernel 2: transpose x [B][C][HW] -> g_xt [B][HW][C], rounding to tf32
// ---------------------------------------------------------------------------
__global__ void transpose_kernel(const float* __restrict__ x) {
    __shared__ float t[32][33];
    const int b  = blockIdx.z;
    const int cb = blockIdx.y * 32;
    const int gb = blockIdx.x * 32;
    const int tx = threadIdx.x, ty = threadIdx.y;
    const float* xb = x + (size_t)b * C_ * HW;
#pragma unroll
    for (int i = 0; i < 32; i += 8)
        t[ty + i][tx] = xb[(size_t)(cb + ty + i) * HW + gb + tx];
    __syncthreads();
    float* xtb = g_xt + (size_t)b * HW * C_;
#pragma unroll
    for (int i = 0; i < 32; i += 8)
        xtb[(size_t)(gb + ty + i) * C_ + cb + tx] = to_tf32(t[tx][ty + i]);
}

// ---------------------------------------------------------------------------
// Kernel 3: persistent fused gather + 9-tap GEMM via mma.sync tf32
// per tile: D[128 px][64 co] = sum_j A_j[128 x 64] * W_j^T, + bias
// warp w: pixel block mb = w>>1 (32 px), co half ch = w&1 (32 co)
// ---------------------------------------------------------------------------
__global__ void __launch_bounds__(THREADS, 1)
latconv_main(const float* __restrict__ wgt,
             const float* __restrict__ bias,
             float* __restrict__ out) {
    extern __shared__ char smem[];
    float*  bsm = (float*)(smem + SMEM_BIAS);
    float*  wsm = (float*)(smem + SMEM_W);

    const int tid = threadIdx.x;
    const int wid = tid >> 5;
    const int lid = tid & 31;
    const int gid = lid >> 2;      // 0..7
    const int tig = lid & 3;       // 0..3
    const int mb  = wid >> 1;      // 0..3  pixel block (32 px)
    const int ch  = wid & 1;       // 0..1  co half (32 co)

    if (tid < C_) bsm[tid] = bias[tid];

    // Stage all weights once: pair layout [tap][ks*4+tig][co].{ci, ci+4}
    for (int e = tid; e < C_ * C_ * 9; e += THREADS) {
        int co  = e / (C_ * 9);
        int r   = e - co * C_ * 9;
        int ci  = r / 9;
        int j   = r - ci * 9;
        float v = to_tf32(wgt[e]);
        int ks  = ci >> 3;
        int rr  = ci & 7;
        int tg  = rr & 3;
        int cmp = rr >> 2;
        wsm[(j * W_TAP_F2 + (ks * 4 + tg) * W_PITCH + co) * 2 + cmp] = v;
    }
    __syncthreads();

    for (int tile = blockIdx.x; tile < N_TILES; tile += gridDim.x) {
        const int b    = tile >> 10;
        const int pt   = tile & (TILES_PER_B - 1);
        const int hRow = pt >> 2;
        const int wB   = (pt & 3) * TILE_P;
        const float* xtb = g_xt + (size_t)b * HW * C_;

        float acc[2][4][4];
#pragma unroll
        for (int mt = 0; mt < 2; ++mt)
#pragma unroll
            for (int nt = 0; nt < 4; ++nt)
#pragma unroll
                for (int q = 0; q < 4; ++q) acc[mt][nt][q] = 0.f;

        // gather tap 0 into buf0
        {
            const int rowBase = (hRow * 3 + 0) * SW_ + 0 + 3 * wB;
            float* ab = (float*)(smem + SMEM_A0);
#pragma unroll
            for (int it = 0; it < 8; ++it) {
                int lin = it * THREADS + tid;
                int p   = lin >> 4;
                int c4  = lin & 15;
                int g   = g_idx32[rowBase + 3 * p];
                float4 v = *(const float4*)(xtb + (size_t)g * C_ + c4 * 4);
                *(float4*)(ab + p * A_PITCH + c4 * 4) = v;
            }
        }
        __syncthreads();

#pragma unroll 1
        for (int j = 0; j < 9; ++j) {
            // prefetch-gather tap j+1 into the other buffer
            if (j < 8) {
                int jn = j + 1;
                int kh = jn / 3, kw = jn - kh * 3;
                const int rowBase = (hRow * 3 + kh) * SW_ + kw + 3 * wB;
                float* ab = (float*)(smem + (((jn & 1) ? SMEM_A1 : SMEM_A0)));
#pragma unroll
                for (int it = 0; it < 8; ++it) {
                    int lin = it * THREADS + tid;
                    int p   = lin >> 4;
                    int c4  = lin & 15;
                    int g   = g_idx32[rowBase + 3 * p];
                    float4 v = *(const float4*)(xtb + (size_t)g * C_ + c4 * 4);
                    *(float4*)(ab + p * A_PITCH + c4 * 4) = v;
                }
            }

            // compute tap j from buf (j&1)
            {
                const float* ab = (const float*)(smem + ((j & 1) ? SMEM_A1 : SMEM_A0));
                const float2* wtap = (const float2*)wsm + j * W_TAP_F2;
#pragma unroll
                for (int ks = 0; ks < 8; ++ks) {
                    float a[2][4];
#pragma unroll
                    for (int mt = 0; mt < 2; ++mt) {
                        int base = (mb * 32 + mt * 16 + gid) * A_PITCH + ks * 8 + tig;
                        a[mt][0] = ab[base];
                        a[mt][1] = ab[base + 8 * A_PITCH];
                        a[mt][2] = ab[base + 4];
                        a[mt][3] = ab[base + 8 * A_PITCH + 4];
                    }
                    const float2* wrow = wtap + (ks * 4 + tig) * W_PITCH + ch * 32;
#pragma unroll
                    for (int nt = 0; nt < 4; ++nt) {
                        float2 bv = wrow[nt * 8 + gid];
                        mma_tf32(acc[0][nt], a[0], bv.x, bv.y);
                        mma_tf32(acc[1][nt], a[1], bv.x, bv.y);
                    }
                }
            }
            __syncthreads();
        }

        // epilogue: stage D transposed [co][px] into buf1 (free after tap 7)
        {
            float* stg = (float*)(smem + SMEM_A1);
#pragma unroll
            for (int mt = 0; mt < 2; ++mt) {
                int p0 = mb * 32 + mt * 16 + gid;
#pragma unroll
                for (int nt = 0; nt < 4; ++nt) {
                    int c0 = ch * 32 + nt * 8 + 2 * tig;
                    float b0 = bsm[c0], b1 = bsm[c0 + 1];
                    stg[c0 * STG_PITCH + p0]            = acc[mt][nt][0] + b0;
                    stg[(c0 + 1) * STG_PITCH + p0]      = acc[mt][nt][1] + b1;
                    stg[c0 * STG_PITCH + p0 + 8]        = acc[mt][nt][2] + b0;
                    stg[(c0 + 1) * STG_PITCH + p0 + 8]  = acc[mt][nt][3] + b1;
                }
            }
        }
        __syncthreads();

        // coalesced global store: 512B per co row
        {
            const float* stg = (const float*)(smem + SMEM_A1);
            const size_t obase = (size_t)b * C_ * HW + (size_t)pt * TILE_P;
#pragma unroll
            for (int e = tid; e < C_ * TILE_P; e += THREADS) {
                int c = e >> 7;
                int p = e & (TILE_P - 1);
                out[obase + (size_t)c * HW + p] = stg[c * STG_PITCH + p];
            }
        }
        __syncthreads();   // stg (buf1) must drain before next tile's gathers
    }
}

// ---------------------------------------------------------------------------
// Launch
// ---------------------------------------------------------------------------
extern "C" void kernel_launch(void* const* d_in, const int* in_sizes, int n_in,
                              void* d_out, int out_size) {
    const float* x    = (const float*)d_in[0];
    const void*  idx  = d_in[1];
    const float* wgt  = (const float*)d_in[2];
    const float* bias = (const float*)d_in[3];
    float* out        = (float*)d_out;

    detect_kernel<<<1, 32>>>((const unsigned int*)idx);
    idx_convert<<<(NIDX + 255) / 256, 256>>>(idx);

    dim3 tb(32, 8);
    dim3 tg(HW / 32, C_ / 32, B_);
    transpose_kernel<<<tg, tb>>>(x);

    cudaFuncSetAttribute(latconv_main, cudaFuncAttributeMaxDynamicSharedMemorySize,
                         SMEM_TOTAL);
    int sm_count = 0;
    cudaDeviceGetAttribute(&sm_count, cudaDevAttrMultiProcessorCount, 0);
    if (sm_count <= 0) sm_count = 148;

    latconv_main<<<sm_count, THREADS, SMEM_TOTAL>>>(wgt, bias, out);
}